// round 11
// baseline (speedup 1.0000x reference)
#include <cuda_runtime.h>
#include <cuda_bf16.h>

// FFT long conv: y[b,:] = (1/N) * linear_conv(x[b], h[b])[:L], N = 2L = 16384.
// One CTA per row, 1024 threads, one radix-16 item per thread per stage.
// Round-9 (byte-identical resubmit; round-9 bench hit the recurring container
// infra failure — rounds 0/2/4 signature — kernel never ran):
// complex arithmetic rewritten in packed f32x2 PTX (add/mul/fma.rn.f32x2,
// sub via fma with -1). A complex value = one 64-bit register pair; butterflies
// halve their fma-pipe op count, twiddle multiplies go 4 ops -> 2 (+amortized prep).
// ptxas never emits FFMA2 from C++ - PTX only.

#define LCONV 8192
#define NFFT  16384
#define LOGN  14
#define NTHR  1024
#define SCALE_F (1.0f / ((float)NFFT * (float)NFFT))

#define PADZ(i) ((i) + ((i) >> 4))
#define ZPAD  (NFFT + (NFFT >> 4))       // 17408 cplx
#define PADT(i) ((i) + ((i) >> 4) + ((i) >> 8))
#define TWPAD (4096 + 256 + 16)          // 4368 float2

typedef unsigned long long cplx;         // (lo = re, hi = im)

__device__ __forceinline__ cplx cpack(float x, float y) {
    cplx r; asm("mov.b64 %0, {%1, %2};" : "=l"(r) : "f"(x), "f"(y)); return r;
}
__device__ __forceinline__ void cunpack(cplx a, float& x, float& y) {
    asm("mov.b64 {%0, %1}, %2;" : "=f"(x), "=f"(y) : "l"(a));
}
__device__ __forceinline__ cplx padd(cplx a, cplx b) {
    cplx r; asm("add.rn.f32x2 %0, %1, %2;" : "=l"(r) : "l"(a), "l"(b)); return r;
}
__device__ __forceinline__ cplx pmul(cplx a, cplx b) {
    cplx r; asm("mul.rn.f32x2 %0, %1, %2;" : "=l"(r) : "l"(a), "l"(b)); return r;
}
__device__ __forceinline__ cplx pfma(cplx a, cplx b, cplx c) {
    cplx r; asm("fma.rn.f32x2 %0, %1, %2, %3;" : "=l"(r) : "l"(a), "l"(b), "l"(c)); return r;
}
// a - b  (fma with packed -1.0f; avoids depending on sub.f32x2 availability)
__device__ __forceinline__ cplx psub(cplx a, cplx b) {
    return pfma(b, 0xBF800000BF800000ULL, a);
}

// twiddle-multiply prep: v*w = (w.x,w.x)*v + (-w.y,w.y)*swap(v)
struct WP { cplx s, t; };
__device__ __forceinline__ WP wprep_f(float wx, float wy) {
    WP p; p.s = cpack(wx, wx); p.t = cpack(-wy, wy); return p;
}
__device__ __forceinline__ WP wprep_conj_f(float wx, float wy) {   // v*conj(w)
    WP p; p.s = cpack(wx, wx); p.t = cpack(wy, -wy); return p;
}
__device__ __forceinline__ WP wprep(cplx w) {
    float x, y; cunpack(w, x, y); return wprep_f(x, y);
}
__device__ __forceinline__ cplx wapply(WP p, cplx v) {
    float x, y; cunpack(v, x, y);
    return pfma(p.t, cpack(y, x), pmul(p.s, v));
}

__device__ __forceinline__ void dif4p(cplx& x0, cplx& x1, cplx& x2, cplx& x3) {
    cplx p = padd(x0, x2), m = psub(x0, x2);
    cplx q = padd(x1, x3), n = psub(x1, x3);
    float nx, ny; cunpack(n, nx, ny);
    cplx mi = cpack(ny, -nx);                 // -i*(x1-x3)
    x0 = padd(p, q); x2 = psub(p, q);
    x1 = padd(m, mi); x3 = psub(m, mi);
}
__device__ __forceinline__ void dit4p(cplx& x0, cplx& x1, cplx& x2, cplx& x3) {
    cplx p = padd(x0, x2), m = psub(x0, x2);
    cplx q = padd(x1, x3), n = psub(x1, x3);
    float nx, ny; cunpack(n, nx, ny);
    cplx pi = cpack(-ny, nx);                 // +i*(x1-x3)
    x0 = padd(p, q); x2 = psub(p, q);
    x1 = padd(m, pi); x3 = psub(m, pi);
}

// pointwise unpack+multiply for a Hermitian pair; orientation-free.
// X = (za+conj(zb))/2, H = -i*(za-conj(zb))/2, Y = X*H*SCALE = (2X)*(2H)*SCALE/4
__device__ __forceinline__ void pwp(cplx& za, cplx& zb) {
    float bx, by; cunpack(zb, bx, by);
    cplx cb = cpack(bx, -by);
    cplx X2 = padd(za, cb);
    cplx D  = psub(za, cb);
    float dx, dy; cunpack(D, dx, dy);
    cplx H2 = cpack(dy, -dx);
    cplx Y = pmul(wapply(wprep(H2), X2),
                  cpack(SCALE_F * 0.25f, SCALE_F * 0.25f));
    float yx, yy; cunpack(Y, yx, yy);
    za = Y;
    zb = cpack(yx, -yy);
}

// one fused middle item; pga/pgb are PRE-PADDED base addresses
__device__ __forceinline__ void pair_item(cplx* z, int pga, int pgb) {
    cplx a0 = z[pga], a1 = z[pga + 1], a2 = z[pga + 2], a3 = z[pga + 3];
    cplx b0 = z[pgb], b1 = z[pgb + 1], b2 = z[pgb + 2], b3 = z[pgb + 3];
    dif4p(a0, a1, a2, a3);
    dif4p(b0, b1, b2, b3);
    pwp(a0, b3); pwp(a1, b2); pwp(a2, b1); pwp(a3, b0);
    dit4p(a0, a1, a2, a3);
    dit4p(b0, b1, b2, b3);
    z[pga] = a0; z[pga + 1] = a1; z[pga + 2] = a2; z[pga + 3] = a3;
    z[pgb] = b0; z[pgb + 1] = b1; z[pgb + 2] = b2; z[pgb + 3] = b3;
}

// generic fused fwd radix-16 stage (spans LM and LM-2), compile-time LM
template<int LM>
__device__ __forceinline__ void fwd16(cplx* __restrict__ z,
                                      const float2* __restrict__ tw, int tid) {
    constexpr int LQ = LM - 4;
    constexpr int QP = 1 << LQ;
    constexpr int Q  = QP << 2;
    constexpr int TS = LOGN - LM;
    const int j    = tid & (QP - 1);
    const int base = ((tid >> LQ) << LM) + j;
    const int pb   = PADZ(base);
    cplx v[4][4];
    #pragma unroll
    for (int a = 0; a < 4; ++a)
        #pragma unroll
        for (int b = 0; b < 4; ++b) {
            const int off = a * Q + b * QP;
            v[a][b] = z[pb + off + (off >> 4)];
        }
    #pragma unroll
    for (int b = 0; b < 4; ++b) {
        float2 wf = tw[PADT((j + b * QP) << TS)];
        WP p1 = wprep_f(wf.x, wf.y);
        cplx w1 = cpack(wf.x, wf.y);
        cplx w2 = wapply(p1, w1);
        WP p2 = wprep(w2);
        cplx w3 = wapply(p2, w1);
        WP p3 = wprep(w3);
        dif4p(v[0][b], v[1][b], v[2][b], v[3][b]);
        v[1][b] = wapply(p1, v[1][b]);
        v[2][b] = wapply(p2, v[2][b]);
        v[3][b] = wapply(p3, v[3][b]);
    }
    {
        float2 wf = tw[PADT(j << (TS + 2))];
        WP p1 = wprep_f(wf.x, wf.y);
        cplx w1 = cpack(wf.x, wf.y);
        cplx w2 = wapply(p1, w1);
        WP p2 = wprep(w2);
        cplx w3 = wapply(p2, w1);
        WP p3 = wprep(w3);
        #pragma unroll
        for (int a = 0; a < 4; ++a) {
            dif4p(v[a][0], v[a][1], v[a][2], v[a][3]);
            v[a][1] = wapply(p1, v[a][1]);
            v[a][2] = wapply(p2, v[a][2]);
            v[a][3] = wapply(p3, v[a][3]);
        }
    }
    #pragma unroll
    for (int a = 0; a < 4; ++a)
        #pragma unroll
        for (int b = 0; b < 4; ++b) {
            const int off = a * Q + b * QP;
            z[pb + off + (off >> 4)] = v[a][b];
        }
}

// generic fused inverse radix-16 stage (spans LMS and LMS+2), compile-time LMS
template<int LMS>
__device__ __forceinline__ void inv16(cplx* __restrict__ z,
                                      const float2* __restrict__ tw, int tid) {
    constexpr int LQS = LMS - 2;
    constexpr int QS  = 1 << LQS;
    constexpr int QL  = 1 << LMS;
    constexpr int TSS = LOGN - LMS;
    const int j    = tid & (QS - 1);
    const int base = ((tid >> LQS) << (LMS + 2)) + j;
    const int pb   = PADZ(base);
    cplx v[4][4];
    #pragma unroll
    for (int a = 0; a < 4; ++a)
        #pragma unroll
        for (int b = 0; b < 4; ++b) {
            const int off = a * QS + b * QL;
            v[a][b] = z[pb + off + (off >> 4)];
        }
    {
        float2 wf = tw[PADT(j << TSS)];
        WP p1 = wprep_conj_f(wf.x, wf.y);
        cplx w1c = cpack(wf.x, -wf.y);
        cplx w2c = wapply(p1, w1c);
        WP p2 = wprep(w2c);
        cplx w3c = wapply(p2, w1c);
        WP p3 = wprep(w3c);
        #pragma unroll
        for (int b = 0; b < 4; ++b) {
            v[1][b] = wapply(p1, v[1][b]);
            v[2][b] = wapply(p2, v[2][b]);
            v[3][b] = wapply(p3, v[3][b]);
            dit4p(v[0][b], v[1][b], v[2][b], v[3][b]);
        }
    }
    #pragma unroll
    for (int a = 0; a < 4; ++a) {
        float2 wf = tw[PADT((j + a * QS) << (TSS - 2))];
        WP p1 = wprep_conj_f(wf.x, wf.y);
        cplx w1c = cpack(wf.x, -wf.y);
        cplx w2c = wapply(p1, w1c);
        WP p2 = wprep(w2c);
        cplx w3c = wapply(p2, w1c);
        WP p3 = wprep(w3c);
        v[a][1] = wapply(p1, v[a][1]);
        v[a][2] = wapply(p2, v[a][2]);
        v[a][3] = wapply(p3, v[a][3]);
        dit4p(v[a][0], v[a][1], v[a][2], v[a][3]);
    }
    #pragma unroll
    for (int a = 0; a < 4; ++a)
        #pragma unroll
        for (int b = 0; b < 4; ++b) {
            const int off = a * QS + b * QL;
            z[pb + off + (off >> 4)] = v[a][b];
        }
}

extern "C" __global__ void __launch_bounds__(NTHR, 1)
fftconv_kernel(const float* __restrict__ xin,
               const float* __restrict__ hin,
               float* __restrict__ yout)
{
    extern __shared__ cplx smz[];
    cplx*   z  = smz;                         // ZPAD cplx (padded data)
    float2* tw = (float2*)(smz + ZPAD);       // TWPAD float2 (padded twiddles)

    const int tid = threadIdx.x;
    const size_t row = blockIdx.x;
    const float* xr = xin + row * LCONV;
    const float* hr = hin + row * LCONV;
    float* yr = yout + row * LCONV;

    // ---- stage-1 gmem loads, issued early so LDG hides under sincos ----
    float2 in0[4], in1[4];
    #pragma unroll
    for (int b = 0; b < 4; ++b) {
        const int i0 = tid + (b << 10);
        in0[b] = make_float2(xr[i0], hr[i0]);
        const int i1 = i0 + 4096;
        in1[b] = make_float2(xr[i1], hr[i1]);
    }

    // ---- twiddles: tw[PADT(t)] = exp(-2*pi*i*t/N), t in [0, N/4) ----
    {
        const float step = -6.28318530717958647692f / (float)NFFT;
        #pragma unroll
        for (int t = tid; t < NFFT / 4; t += NTHR) {
            float s, c;
            __sincosf(step * (float)t, &s, &c);
            tw[PADT(t)] = make_float2(c, s);
        }
    }
    __syncthreads();

    // ---- fwd stage lm=14, fused with input; indices >= 8192 are zero ----
    {
        const int j  = tid;
        const int pb = PADZ(j);
        cplx v[4][4];
        #pragma unroll
        for (int b = 0; b < 4; ++b) {
            float2 wf = tw[PADT(j + (b << 10))];
            WP p1 = wprep_f(wf.x, wf.y);
            cplx w1 = cpack(wf.x, wf.y);
            cplx w2 = wapply(p1, w1);
            WP p2 = wprep(w2);
            cplx w3 = wapply(p2, w1);
            WP p3 = wprep(w3);
            cplx X0 = cpack(in0[b].x, in0[b].y);
            cplx X1 = cpack(in1[b].x, in1[b].y);
            v[0][b] = padd(X0, X1);
            v[1][b] = wapply(p1, padd(X0, cpack(in1[b].y, -in1[b].x)));  // x0 - i*x1
            v[2][b] = wapply(p2, psub(X0, X1));
            v[3][b] = wapply(p3, padd(X0, cpack(-in1[b].y, in1[b].x)));  // x0 + i*x1
        }
        {
            float2 wf = tw[PADT(j << 2)];
            WP p1 = wprep_f(wf.x, wf.y);
            cplx w1 = cpack(wf.x, wf.y);
            cplx w2 = wapply(p1, w1);
            WP p2 = wprep(w2);
            cplx w3 = wapply(p2, w1);
            WP p3 = wprep(w3);
            #pragma unroll
            for (int a = 0; a < 4; ++a) {
                dif4p(v[a][0], v[a][1], v[a][2], v[a][3]);
                v[a][1] = wapply(p1, v[a][1]);
                v[a][2] = wapply(p2, v[a][2]);
                v[a][3] = wapply(p3, v[a][3]);
            }
        }
        #pragma unroll
        for (int a = 0; a < 4; ++a)
            #pragma unroll
            for (int b = 0; b < 4; ++b) {
                const int off = a * 4096 + b * 1024;
                z[pb + off + (off >> 4)] = v[a][b];
            }
    }
    __syncthreads();

    // ---- fwd stages lm = 10, 6 ----
    fwd16<10>(z, tw, tid);
    __syncthreads();
    fwd16<6>(z, tw, tid);
    __syncthreads();

    // ---- FUSED middle: fwd lm=2 radix-4 + pointwise + inv lm=2 radix-4 ----
    {
        #pragma unroll 1
        for (int m = LOGN; m >= 4; m -= 2) {
            const int S4 = 1 << (m - 2);
            // branch 1: [S4, 2*S4) <-> [3*S4, 4*S4)
            #pragma unroll 1
            for (int it = tid; it < (S4 >> 2); it += NTHR) {
                const int ga = S4 + 4 * it;
                const int gb = 4 * S4 - 4 - 4 * it;
                pair_item(z, PADZ(ga), PADZ(gb));
            }
            // branch 2: [2*S4, 3*S4) pairs internally (needs >= 2 groups)
            if (S4 >= 16) {
                #pragma unroll 1
                for (int it = tid; it < (S4 >> 3); it += NTHR) {
                    const int ga = 2 * S4 + 4 * it;
                    const int gb = 3 * S4 - 4 - 4 * it;
                    pair_item(z, PADZ(ga), PADZ(gb));
                }
            }
        }
        // special: group [0..3] (selfs k=0 @0, k=N/2 @2; pair (1,3))
        if (tid == NTHR - 1) {
            cplx a0 = z[0], a1 = z[1], a2 = z[2], a3 = z[3];
            dif4p(a0, a1, a2, a3);
            float a0x, a0y, a2x, a2y;
            cunpack(a0, a0x, a0y); cunpack(a2, a2x, a2y);
            a0 = cpack(a0x * a0y * SCALE_F, 0.0f);
            a2 = cpack(a2x * a2y * SCALE_F, 0.0f);
            pwp(a1, a3);
            dit4p(a0, a1, a2, a3);
            z[0] = a0; z[1] = a1; z[2] = a2; z[3] = a3;
        }
        // special: group [8..11] (S4=4 middle; pairs (8,11),(9,10))
        if (tid == NTHR - 2) {
            cplx a0 = z[8], a1 = z[9], a2 = z[10], a3 = z[11];
            dif4p(a0, a1, a2, a3);
            pwp(a0, a3); pwp(a1, a2);
            dit4p(a0, a1, a2, a3);
            z[8] = a0; z[9] = a1; z[10] = a2; z[11] = a3;
        }
    }
    __syncthreads();

    // ---- inverse stages lm_s = 4, 8 ----
    inv16<4>(z, tw, tid);
    __syncthreads();
    inv16<8>(z, tw, tid);
    __syncthreads();

    // ---- inverse stage lm_s = 12, fused with gmem store ----
    // outputs at j + 1024*a + 4096*b; b in {0,1} covers [0, 8192) exactly.
    {
        const int j  = tid;      // qs = 1024, ql = 4096, tss = 2
        const int pb = PADZ(j);
        cplx v[4][4];
        #pragma unroll
        for (int a = 0; a < 4; ++a)
            #pragma unroll
            for (int b = 0; b < 4; ++b) {
                const int off = (a << 10) + (b << 12);
                v[a][b] = z[pb + off + (off >> 4)];
            }
        {
            float2 wf = tw[PADT(j << 2)];
            WP p1 = wprep_conj_f(wf.x, wf.y);
            cplx w1c = cpack(wf.x, -wf.y);
            cplx w2c = wapply(p1, w1c);
            WP p2 = wprep(w2c);
            cplx w3c = wapply(p2, w1c);
            WP p3 = wprep(w3c);
            #pragma unroll
            for (int b = 0; b < 4; ++b) {
                v[1][b] = wapply(p1, v[1][b]);
                v[2][b] = wapply(p2, v[2][b]);
                v[3][b] = wapply(p3, v[3][b]);
                dit4p(v[0][b], v[1][b], v[2][b], v[3][b]);
            }
        }
        #pragma unroll
        for (int a = 0; a < 4; ++a) {
            float2 wc = tw[PADT(j + (a << 10))];
            float w1x = wc.x, w1y = -wc.y;                     // conj
            float w2x = fmaf(w1x, w1x, -w1y * w1y);
            float w2y = 2.0f * w1x * w1y;
            float w3x = fmaf(w2x, w1x, -w2y * w1y);
            float w3y = fmaf(w2x, w1y,  w2y * w1x);
            float c0x, c0y, v1x, v1y, v2x, v2y, v3x, v3y;
            cunpack(v[a][0], c0x, c0y);
            cunpack(v[a][1], v1x, v1y);
            cunpack(v[a][2], v2x, v2y);
            cunpack(v[a][3], v3x, v3y);
            float c1x = fmaf(v1x, w1x, -v1y * w1y);
            float c1y = fmaf(v1x, w1y,  v1y * w1x);
            float c2x = fmaf(v2x, w2x, -v2y * w2y);            // Re only
            float c3x = fmaf(v3x, w3x, -v3y * w3y);
            float c3y = fmaf(v3x, w3y,  v3y * w3x);
            // b=0: Re(s02p + s13p); b=1: Re(s02m + i*(c1-c3))
            float y0 = (c0x + c2x) + (c1x + c3x);
            float y1 = (c0x - c2x) - (c1y - c3y);
            yr[j + (a << 10)]        = y0;
            yr[j + (a << 10) + 4096] = y1;
        }
    }
}

extern "C" void kernel_launch(void* const* d_in, const int* in_sizes, int n_in,
                              void* d_out, int out_size) {
    const float* x = (const float*)d_in[0];
    const float* h = (const float*)d_in[1];
    float* y = (float*)d_out;

    const int B = in_sizes[0] / LCONV;
    const size_t smem_bytes = (size_t)ZPAD * sizeof(cplx)
                            + (size_t)TWPAD * sizeof(float2);  // ~174 KB

    cudaFuncSetAttribute(fftconv_kernel,
                         cudaFuncAttributeMaxDynamicSharedMemorySize,
                         (int)smem_bytes);
    fftconv_kernel<<<B, NTHR, smem_bytes>>>(x, h, y);
}